// round 1
// baseline (speedup 1.0000x reference)
#include <cuda_runtime.h>
#include <cuda_pipeline.h>
#include <cstdint>

// Problem constants
#define BATCH 8
#define CH    128          // CIN == COUT == 128
#define DIM   32
#define PLANE (DIM*DIM)        // 1024
#define VOL   (DIM*DIM*DIM)    // 32768
#define TAPS  27

// Scratch (no cudaMalloc allowed)
__device__ float g_wT[CH*CH*TAPS];   // [ic][oc][tap]
__device__ float g_demod[BATCH*CH];  // [b][oc]

// ---------------------------------------------------------------------------
// packed fp32 helpers (sm_100+ f32x2 path; ptxas never auto-fuses this)
// ---------------------------------------------------------------------------
__device__ __forceinline__ unsigned long long pk(float lo, float hi) {
    unsigned long long r;
    asm("mov.b64 %0, {%1, %2};" : "=l"(r) : "f"(lo), "f"(hi));
    return r;
}
__device__ __forceinline__ void upk(unsigned long long v, float& lo, float& hi) {
    asm("mov.b64 {%0, %1}, %2;" : "=f"(lo), "=f"(hi) : "l"(v));
}
#define FFMA2(d, a, b) \
    asm("fma.rn.f32x2 %0, %1, %2, %0;" : "+l"(d) : "l"(a), "l"(b))

// ---------------------------------------------------------------------------
// Kernel 1: transpose weights [O][I][27] -> [I][O][27] for coalesced per-ic reads
// ---------------------------------------------------------------------------
__global__ void wt_kernel(const float* __restrict__ w) {
    int idx = blockIdx.x * 256 + threadIdx.x;
    if (idx < CH*CH*TAPS) {
        int o = idx / (CH*TAPS);
        int r = idx - o * (CH*TAPS);
        int i = r / TAPS;
        int k = r - i * TAPS;
        g_wT[(i*CH + o)*TAPS + k] = w[idx];
    }
}

// ---------------------------------------------------------------------------
// Kernel 2: demod d[b,o] = rsqrt( sum_i (1+y[b,i])^2 * sum_k w[o,i,k]^2 + eps )
// grid: (128 o, 8 b), block: 128 threads (one per ic)
// ---------------------------------------------------------------------------
__global__ void demod_kernel(const float* __restrict__ y, const float* __restrict__ w) {
    int o = blockIdx.x, b = blockIdx.y, i = threadIdx.x;
    float s = 1.f + y[b*CH + i];
    const float* wp = w + (size_t)(o*CH + i) * TAPS;
    float a = 0.f;
    #pragma unroll
    for (int k = 0; k < TAPS; k++) { float v = wp[k]; a += v*v; }
    a *= s*s;
    __shared__ float red[CH];
    red[i] = a;
    __syncthreads();
    #pragma unroll
    for (int off = 64; off > 0; off >>= 1) {
        if (i < off) red[i] += red[i + off];
        __syncthreads();
    }
    if (i == 0) g_demod[b*CH + o] = rsqrtf(red[0] + 1e-8f);
}

// ---------------------------------------------------------------------------
// Kernel 3: shared-weight 3D conv, input-scale folded into weight tile,
// demod folded into stores. Block: 64 oc x (8 rows x 32 cols) at one (b, z).
// ---------------------------------------------------------------------------
#define XSW 34            // smem row width (cols -1..32) ; 136B rows keep LDS.64 aligned
#define XN  (3*10*XSW)    // 1020 elements per ic slab
#define WN  (64*TAPS)     // 1728 weights per ic per oc-half

__global__ void __launch_bounds__(256, 2)
conv_kernel(const float* __restrict__ x, const float* __restrict__ y,
            float* __restrict__ out) {
    __shared__ __align__(16) float xs[2][3][10][XSW];
    __shared__ float ws[2][WN];
    __shared__ float ysc[CH];

    const int tid = threadIdx.x;
    const int bx  = blockIdx.x;            // 0..7
    const int z   = blockIdx.y;            // 0..31
    const int b   = blockIdx.z;            // 0..7
    const int oc_base  = (bx & 1) * 64;
    const int row_base = (bx >> 1) * 8;

    if (tid < CH) ysc[tid] = 1.f + y[b*CH + tid];
    __syncthreads();

    const int ocg = tid >> 5;              // warp id = oc group (weight LDS broadcasts)
    const int spg = tid & 31;
    const int lr  = spg >> 2;              // local row 0..7
    const int cb  = (spg & 3) * 8;         // col base 0/8/16/24

    const float* xb = x + (size_t)b * CH * VOL;

    auto prefetch_x = [&](int ic, int buf) {
        const float* xc = xb + (size_t)ic * VOL;
        for (int t = tid; t < XN; t += 256) {
            int p  = t / (10*XSW);
            int r2 = t - p * (10*XSW);
            int r  = r2 / XSW;
            int c  = r2 - r * XSW;
            int gz = z - 1 + p;
            int gy = row_base - 1 + r;
            int gx = c - 1;
            bool ok = ((unsigned)gz < (unsigned)DIM) &
                      ((unsigned)gy < (unsigned)DIM) &
                      ((unsigned)gx < (unsigned)DIM);
            const float* src = ok ? (xc + gz*PLANE + gy*DIM + gx) : xc;
            __pipeline_memcpy_async(&xs[buf][p][r][c], src, 4, ok ? 0 : 4);
        }
    };

    float wreg[7];
    auto ldg_w = [&](int ic) {
        const float* wp = g_wT + ((size_t)ic * CH + oc_base) * TAPS;
        #pragma unroll
        for (int j = 0; j < 7; j++) {
            int t = tid + j * 256;
            wreg[j] = (t < WN) ? wp[t] : 0.f;
        }
    };
    auto sts_w = [&](int ic, int buf) {
        float s = ysc[ic];
        #pragma unroll
        for (int j = 0; j < 7; j++) {
            int t = tid + j * 256;
            if (t < WN) ws[buf][t] = wreg[j] * s;
        }
    };

    unsigned long long acc[8][4];
    #pragma unroll
    for (int u = 0; u < 8; u++)
        #pragma unroll
        for (int p = 0; p < 4; p++) acc[u][p] = 0ull;

    // prologue: stage ic=0
    ldg_w(0);
    prefetch_x(0, 0);
    __pipeline_commit();
    sts_w(0, 0);

    for (int ic = 0; ic < CH; ++ic) {
        const int cur = ic & 1, nxt = cur ^ 1;
        __pipeline_wait_prior(0);
        __syncthreads();                       // cur data ready; nxt buffer free

        if (ic + 1 < CH) {
            ldg_w(ic + 1);                     // global loads issued early
            prefetch_x(ic + 1, nxt);
            __pipeline_commit();
        }

        const float* wsc = ws[cur];
        for (int dz = 0; dz < 3; ++dz) {
            #pragma unroll
            for (int dy = 0; dy < 3; ++dy) {
                const float* xrow = &xs[cur][dz][lr + dy][cb];
                unsigned long long e[5];
                #pragma unroll
                for (int m = 0; m < 5; m++)
                    e[m] = *(const unsigned long long*)(xrow + 2*m);
                unsigned long long xp[9];
                #pragma unroll
                for (int m = 0; m < 5; m++) xp[2*m] = e[m];
                #pragma unroll
                for (int m = 0; m < 4; m++) {
                    float l0, h0, l1, h1;
                    upk(e[m],   l0, h0);
                    upk(e[m+1], l1, h1);
                    xp[2*m + 1] = pk(h0, l1);
                }
                const int tb = dz*9 + dy*3;
                #pragma unroll
                for (int u = 0; u < 8; ++u) {
                    const float* wp = wsc + (ocg*8 + u)*TAPS + tb;   // broadcast LDS
                    unsigned long long w0 = pk(wp[0], wp[0]);
                    unsigned long long w1 = pk(wp[1], wp[1]);
                    unsigned long long w2 = pk(wp[2], wp[2]);
                    #pragma unroll
                    for (int p = 0; p < 4; ++p) {
                        FFMA2(acc[u][p], w0, xp[2*p]);
                        FFMA2(acc[u][p], w1, xp[2*p + 1]);
                        FFMA2(acc[u][p], w2, xp[2*p + 2]);
                    }
                }
            }
        }

        if (ic + 1 < CH) sts_w(ic + 1, nxt);   // LDGs long since landed; no stall
    }

    // epilogue: demod + float4 stores
    const float* dm = g_demod + b*CH + oc_base + ocg*8;
    float* ob = out + (((size_t)b*CH + oc_base + ocg*8) * DIM + z) * PLANE
                    + (row_base + lr) * DIM + cb;
    #pragma unroll
    for (int u = 0; u < 8; ++u) {
        float d = dm[u];
        float a0, a1;
        float4 v0, v1;
        upk(acc[u][0], a0, a1); v0.x = a0*d; v0.y = a1*d;
        upk(acc[u][1], a0, a1); v0.z = a0*d; v0.w = a1*d;
        upk(acc[u][2], a0, a1); v1.x = a0*d; v1.y = a1*d;
        upk(acc[u][3], a0, a1); v1.z = a0*d; v1.w = a1*d;
        float* op = ob + (size_t)u * DIM * PLANE;
        *(float4*)(op)     = v0;
        *(float4*)(op + 4) = v1;
    }
}

// ---------------------------------------------------------------------------
// launch: inputs are x [8,128,32,32,32] f32, y [8,128] f32, weight [128,128,27] f32
// ---------------------------------------------------------------------------
extern "C" void kernel_launch(void* const* d_in, const int* in_sizes, int n_in,
                              void* d_out, int out_size) {
    const float* x = (const float*)d_in[0];
    const float* y = (const float*)d_in[1];
    const float* w = (const float*)d_in[2];
    float* out = (float*)d_out;

    wt_kernel<<<(CH*CH*TAPS + 255) / 256, 256>>>(w);
    demod_kernel<<<dim3(CH, BATCH), CH>>>(y, w);
    conv_kernel<<<dim3(8, DIM, BATCH), 256>>>(x, y, out);
}